// round 1
// baseline (speedup 1.0000x reference)
#include <cuda_runtime.h>

#define BB 2
#define SS 2048
#define DD 512
#define HH 8
#define DKK 64
#define MROWS (BB*SS)   // 4096

// Scratch (static device globals — no allocation allowed)
__device__ float g_q[MROWS * DD];
__device__ float g_k[MROWS * DD];
__device__ float g_v[MROWS * DD];
__device__ float g_x[MROWS * DD];

// ---------------------------------------------------------------------------
// GEMM: C[M,N] = A[M,K] @ W[N,K]^T + bias[N]
// Tiles: 64x64x16, 256 threads, 4x4 per-thread microtile.
// A and W are both K-contiguous (row-major), staged transposed into smem so
// the inner loop is 2x LDS.128 per 16 FFMA.
// ---------------------------------------------------------------------------
__global__ __launch_bounds__(256) void gemm_bias_kernel(
    const float* __restrict__ A, const float* __restrict__ W,
    const float* __restrict__ bias, float* __restrict__ C,
    int M, int N, int K)
{
    __shared__ float As[16][68];  // [k][m], +4 pad keeps 16B alignment, kills conflicts
    __shared__ float Ws[16][68];  // [k][n]

    const int tid = threadIdx.x;
    const int tx = tid & 15;        // n-dir
    const int ty = tid >> 4;        // m-dir
    const int m0 = blockIdx.y * 64;
    const int n0 = blockIdx.x * 64;

    float acc[4][4] = {};

    const int lr = tid >> 2;   // row 0..63 for cooperative loads
    const int lq = tid & 3;    // float4 index within 16-wide k slice

    for (int k0 = 0; k0 < K; k0 += 16) {
        float4 va = *(const float4*)&A[(size_t)(m0 + lr) * K + k0 + lq * 4];
        float4 vw = *(const float4*)&W[(size_t)(n0 + lr) * K + k0 + lq * 4];
        As[lq * 4 + 0][lr] = va.x; As[lq * 4 + 1][lr] = va.y;
        As[lq * 4 + 2][lr] = va.z; As[lq * 4 + 3][lr] = va.w;
        Ws[lq * 4 + 0][lr] = vw.x; Ws[lq * 4 + 1][lr] = vw.y;
        Ws[lq * 4 + 2][lr] = vw.z; Ws[lq * 4 + 3][lr] = vw.w;
        __syncthreads();

        #pragma unroll
        for (int k = 0; k < 16; k++) {
            float4 a = *(const float4*)&As[k][ty * 4];
            float4 b = *(const float4*)&Ws[k][tx * 4];
            acc[0][0] += a.x * b.x; acc[0][1] += a.x * b.y;
            acc[0][2] += a.x * b.z; acc[0][3] += a.x * b.w;
            acc[1][0] += a.y * b.x; acc[1][1] += a.y * b.y;
            acc[1][2] += a.y * b.z; acc[1][3] += a.y * b.w;
            acc[2][0] += a.z * b.x; acc[2][1] += a.z * b.y;
            acc[2][2] += a.z * b.z; acc[2][3] += a.z * b.w;
            acc[3][0] += a.w * b.x; acc[3][1] += a.w * b.y;
            acc[3][2] += a.w * b.z; acc[3][3] += a.w * b.w;
        }
        __syncthreads();
    }

    #pragma unroll
    for (int i = 0; i < 4; i++) {
        const int m = m0 + ty * 4 + i;
        #pragma unroll
        for (int j = 0; j < 4; j++) {
            const int n = n0 + tx * 4 + j;
            C[(size_t)m * N + n] = acc[i][j] + bias[n];
        }
    }
}

// ---------------------------------------------------------------------------
// Flash attention (causal), fp32.
// Grid: (S/64 q-tiles, B*H). Block: 64 threads, one thread per query row.
// q row lives in registers (pre-scaled by 1/sqrt(DK)); K/V tiles (32x64) in
// smem, read as broadcast LDS.128 (1 LDS per 4 FFMA).
// ---------------------------------------------------------------------------
#define BN 32

__global__ __launch_bounds__(64) void attn_kernel(
    const float* __restrict__ gq, const float* __restrict__ gk,
    const float* __restrict__ gv, float* __restrict__ gx)
{
    __shared__ float Ks[BN][DKK];
    __shared__ float Vs[BN][DKK];

    const int tid = threadIdx.x;          // 0..63 = query row within tile
    const int qt  = blockIdx.x;           // q tile
    const int bh  = blockIdx.y;
    const int b   = bh / HH;
    const int h   = bh % HH;
    const int q_glob = qt * 64 + tid;

    const float scale = 0.125f;           // 1/sqrt(64)

    const float* qptr = gq + ((size_t)b * SS + q_glob) * DD + h * DKK;
    float q[DKK];
    #pragma unroll
    for (int d = 0; d < DKK; d += 4) {
        float4 v = *(const float4*)&qptr[d];
        q[d]   = v.x * scale; q[d+1] = v.y * scale;
        q[d+2] = v.z * scale; q[d+3] = v.w * scale;
    }

    float acc[DKK];
    #pragma unroll
    for (int d = 0; d < DKK; d++) acc[d] = 0.f;
    float mrow = -1e30f, l = 0.f;

    const float* kbase = gk + (size_t)b * SS * DD + h * DKK;
    const float* vbase = gv + (size_t)b * SS * DD + h * DKK;

    const int nkt = (qt * 64 + 64) / BN;   // key tiles needed (causal)

    for (int kt = 0; kt < nkt; kt++) {
        const int k0 = kt * BN;

        __syncthreads();  // protect previous tile's reads
        // cooperative load: BN*DKK/4 = 512 float4, 64 threads -> 8 each
        #pragma unroll
        for (int i = tid; i < BN * DKK / 4; i += 64) {
            const int row = i >> 4;        // /16
            const int c   = i & 15;
            ((float4*)Ks[row])[c] = *(const float4*)&kbase[(size_t)(k0 + row) * DD + c * 4];
            ((float4*)Vs[row])[c] = *(const float4*)&vbase[(size_t)(k0 + row) * DD + c * 4];
        }
        __syncthreads();

        float s[BN];
        #pragma unroll
        for (int kk = 0; kk < BN; kk++) {
            float a0 = 0.f, a1 = 0.f, a2 = 0.f, a3 = 0.f;
            #pragma unroll
            for (int d = 0; d < DKK; d += 4) {
                float4 kv = *(const float4*)&Ks[kk][d];
                a0 += q[d]   * kv.x; a1 += q[d+1] * kv.y;
                a2 += q[d+2] * kv.z; a3 += q[d+3] * kv.w;
            }
            s[kk] = (a0 + a1) + (a2 + a3);
        }

        // causal mask (only the tiles straddling the diagonal need it)
        if (k0 + BN - 1 > q_glob) {
            #pragma unroll
            for (int kk = 0; kk < BN; kk++)
                if (k0 + kk > q_glob) s[kk] = -1e30f;
        }

        float mnew = mrow;
        #pragma unroll
        for (int kk = 0; kk < BN; kk++) mnew = fmaxf(mnew, s[kk]);
        const float corr = __expf(mrow - mnew);
        mrow = mnew;
        l *= corr;
        #pragma unroll
        for (int d = 0; d < DKK; d++) acc[d] *= corr;

        #pragma unroll
        for (int kk = 0; kk < BN; kk++) {
            s[kk] = __expf(s[kk] - mnew);
            l += s[kk];
        }

        #pragma unroll
        for (int kk = 0; kk < BN; kk++) {
            const float p = s[kk];
            #pragma unroll
            for (int d = 0; d < DKK; d += 4) {
                float4 vv = *(const float4*)&Vs[kk][d];
                acc[d]   += p * vv.x; acc[d+1] += p * vv.y;
                acc[d+2] += p * vv.z; acc[d+3] += p * vv.w;
            }
        }
    }

    const float inv = 1.f / l;
    float* optr = gx + ((size_t)b * SS + q_glob) * DD + h * DKK;
    #pragma unroll
    for (int d = 0; d < DKK; d += 4) {
        float4 o;
        o.x = acc[d] * inv;   o.y = acc[d+1] * inv;
        o.z = acc[d+2] * inv; o.w = acc[d+3] * inv;
        *(float4*)&optr[d] = o;
    }
}

// ---------------------------------------------------------------------------
// Launch
// ---------------------------------------------------------------------------
extern "C" void kernel_launch(void* const* d_in, const int* in_sizes, int n_in,
                              void* d_out, int out_size)
{
    const float* query = (const float*)d_in[0];
    const float* key   = (const float*)d_in[1];
    const float* value = (const float*)d_in[2];
    // d_in[3] = mask (deterministic causal tril) — implemented analytically
    const float* Wq = (const float*)d_in[4];
    const float* bq = (const float*)d_in[5];
    const float* Wk = (const float*)d_in[6];
    const float* bk = (const float*)d_in[7];
    const float* Wv = (const float*)d_in[8];
    const float* bv = (const float*)d_in[9];
    const float* Wo = (const float*)d_in[10];
    const float* bo = (const float*)d_in[11];
    float* out = (float*)d_out;

    float *gq, *gk, *gv, *gx;
    cudaGetSymbolAddress((void**)&gq, g_q);
    cudaGetSymbolAddress((void**)&gk, g_k);
    cudaGetSymbolAddress((void**)&gv, g_v);
    cudaGetSymbolAddress((void**)&gx, g_x);

    const dim3 ggrid(DD / 64, MROWS / 64);   // (8, 64)
    gemm_bias_kernel<<<ggrid, 256>>>(query, Wq, bq, gq, MROWS, DD, DD);
    gemm_bias_kernel<<<ggrid, 256>>>(key,   Wk, bk, gk, MROWS, DD, DD);
    gemm_bias_kernel<<<ggrid, 256>>>(value, Wv, bv, gv, MROWS, DD, DD);

    const dim3 agrid(SS / 64, BB * HH);      // (32, 16)
    attn_kernel<<<agrid, 64>>>(gq, gk, gv, gx);

    gemm_bias_kernel<<<ggrid, 256>>>(gx, Wo, bo, out, MROWS, DD, DD);
}

// round 5
// speedup vs baseline: 1.2804x; 1.2804x over previous
#include <cuda_runtime.h>

#define BB 2
#define SS 2048
#define DD 512
#define HH 8
#define DKK 64
#define MROWS (BB*SS)   // 4096

// Scratch (static device globals — no allocation allowed)
__device__ float g_q[MROWS * DD];
__device__ float g_k[MROWS * DD];
__device__ float g_v[MROWS * DD];
__device__ float g_x[MROWS * DD];

// ---------------------------------------------------------------------------
// GEMM: C[M,N] = A[M,K] @ W[N,K]^T + bias[N]   (unchanged — ~29 TF/s already)
// ---------------------------------------------------------------------------
__global__ __launch_bounds__(256) void gemm_bias_kernel(
    const float* __restrict__ A, const float* __restrict__ W,
    const float* __restrict__ bias, float* __restrict__ C,
    int M, int N, int K)
{
    __shared__ float As[16][68];
    __shared__ float Ws[16][68];

    const int tid = threadIdx.x;
    const int tx = tid & 15;
    const int ty = tid >> 4;
    const int m0 = blockIdx.y * 64;
    const int n0 = blockIdx.x * 64;

    float acc[4][4] = {};

    const int lr = tid >> 2;
    const int lq = tid & 3;

    for (int k0 = 0; k0 < K; k0 += 16) {
        float4 va = *(const float4*)&A[(size_t)(m0 + lr) * K + k0 + lq * 4];
        float4 vw = *(const float4*)&W[(size_t)(n0 + lr) * K + k0 + lq * 4];
        As[lq * 4 + 0][lr] = va.x; As[lq * 4 + 1][lr] = va.y;
        As[lq * 4 + 2][lr] = va.z; As[lq * 4 + 3][lr] = va.w;
        Ws[lq * 4 + 0][lr] = vw.x; Ws[lq * 4 + 1][lr] = vw.y;
        Ws[lq * 4 + 2][lr] = vw.z; Ws[lq * 4 + 3][lr] = vw.w;
        __syncthreads();

        #pragma unroll
        for (int k = 0; k < 16; k++) {
            float4 a = *(const float4*)&As[k][ty * 4];
            float4 b = *(const float4*)&Ws[k][tx * 4];
            acc[0][0] += a.x * b.x; acc[0][1] += a.x * b.y;
            acc[0][2] += a.x * b.z; acc[0][3] += a.x * b.w;
            acc[1][0] += a.y * b.x; acc[1][1] += a.y * b.y;
            acc[1][2] += a.y * b.z; acc[1][3] += a.y * b.w;
            acc[2][0] += a.z * b.x; acc[2][1] += a.z * b.y;
            acc[2][2] += a.z * b.z; acc[2][3] += a.z * b.w;
            acc[3][0] += a.w * b.x; acc[3][1] += a.w * b.y;
            acc[3][2] += a.w * b.z; acc[3][3] += a.w * b.w;
        }
        __syncthreads();
    }

    #pragma unroll
    for (int i = 0; i < 4; i++) {
        const int m = m0 + ty * 4 + i;
        #pragma unroll
        for (int j = 0; j < 4; j++) {
            const int n = n0 + tx * 4 + j;
            C[(size_t)m * N + n] = acc[i][j] + bias[n];
        }
    }
}

// ---------------------------------------------------------------------------
// Flash attention (causal), fp32, 2-lanes-per-query-row split.
// Block: 128 threads (4 warps), 64 query rows/block.
// Warp w handles rows w*16..w*16+15; lanes l and l^16 each own half the 64
// dims of one row, interleaved at float4 granularity (chunk parity) so the
// two halves' LDS hit different banks. Score = partial dot + shfl.xor(16).
// Per-thread state: q[32]+acc[32]+s[32] => ~3 blocks/SM resident.
// ---------------------------------------------------------------------------
#define BN 32
#define BQ 64

__global__ __launch_bounds__(128, 3) void attn_kernel(
    const float* __restrict__ gq, const float* __restrict__ gk,
    const float* __restrict__ gv, float* __restrict__ gx)
{
    __shared__ float Ks[BN][DKK];   // 8 KB
    __shared__ float Vs[BN][DKK];   // 8 KB

    const int tid  = threadIdx.x;
    const int lane = tid & 31;
    const int warp = tid >> 5;
    const int row  = warp * 16 + (lane & 15);   // 0..63 query row in tile
    const int half = lane >> 4;                 // 0/1: which dim-half this lane owns

    const int qt = blockIdx.x;
    const int bh = blockIdx.y;
    const int b  = bh / HH;
    const int h  = bh % HH;
    const int q_glob = qt * BQ + row;

    const float scale = 0.125f;   // 1/sqrt(64)

    // Owned dims: float4 chunks c=0..7 -> global chunk (2c+half), dims (2c+half)*4..+3
    const float4* qptr4 = (const float4*)(gq + ((size_t)b * SS + q_glob) * DD + h * DKK);
    float q[32];
    #pragma unroll
    for (int c = 0; c < 8; c++) {
        float4 v = qptr4[2 * c + half];
        q[4*c+0] = v.x * scale; q[4*c+1] = v.y * scale;
        q[4*c+2] = v.z * scale; q[4*c+3] = v.w * scale;
    }

    float acc[32];
    #pragma unroll
    for (int d = 0; d < 32; d++) acc[d] = 0.f;
    float mrow = -1e30f, l = 0.f;

    const float* kbase = gk + (size_t)b * SS * DD + h * DKK;
    const float* vbase = gv + (size_t)b * SS * DD + h * DKK;

    const int nkt = (qt + 1) * (BQ / BN);   // causal: key tiles needed

    for (int kt = 0; kt < nkt; kt++) {
        const int k0 = kt * BN;

        __syncthreads();
        // cooperative load: BN rows x 16 float4 each for K and V; 128 threads
        #pragma unroll
        for (int i = tid; i < BN * 16; i += 128) {
            const int r = i >> 4;
            const int c = i & 15;
            ((float4*)Ks[r])[c] = ((const float4*)&kbase[(size_t)(k0 + r) * DD])[c];
            ((float4*)Vs[r])[c] = ((const float4*)&vbase[(size_t)(k0 + r) * DD])[c];
        }
        __syncthreads();

        // QK^T partial dots over owned half, then cross-lane reduce
        float s[BN];
        #pragma unroll
        for (int kk = 0; kk < BN; kk++) {
            float a0 = 0.f, a1 = 0.f, a2 = 0.f, a3 = 0.f;
            #pragma unroll
            for (int c = 0; c < 8; c++) {
                float4 kv = ((const float4*)Ks[kk])[2 * c + half];
                a0 += q[4*c+0] * kv.x; a1 += q[4*c+1] * kv.y;
                a2 += q[4*c+2] * kv.z; a3 += q[4*c+3] * kv.w;
            }
            s[kk] = (a0 + a1) + (a2 + a3);
        }
        #pragma unroll
        for (int kk = 0; kk < BN; kk++)
            s[kk] += __shfl_xor_sync(0xffffffffu, s[kk], 16);

        // causal mask (only tiles straddling the diagonal)
        if (k0 + BN - 1 > q_glob) {
            #pragma unroll
            for (int kk = 0; kk < BN; kk++)
                if (k0 + kk > q_glob) s[kk] = -1e30f;
        }

        float mnew = mrow;
        #pragma unroll
        for (int kk = 0; kk < BN; kk++) mnew = fmaxf(mnew, s[kk]);
        const float corr = __expf(mrow - mnew);
        mrow = mnew;
        l *= corr;
        #pragma unroll
        for (int d = 0; d < 32; d++) acc[d] *= corr;

        #pragma unroll
        for (int kk = 0; kk < BN; kk++) {
            s[kk] = __expf(s[kk] - mnew);
            l += s[kk];
        }

        // PV over owned half
        #pragma unroll
        for (int kk = 0; kk < BN; kk++) {
            const float p = s[kk];
            #pragma unroll
            for (int c = 0; c < 8; c++) {
                float4 vv = ((const float4*)Vs[kk])[2 * c + half];
                acc[4*c+0] += p * vv.x; acc[4*c+1] += p * vv.y;
                acc[4*c+2] += p * vv.z; acc[4*c+3] += p * vv.w;
            }
        }
    }

    const float inv = 1.f / l;
    float4* optr4 = (float4*)(gx + ((size_t)b * SS + q_glob) * DD + h * DKK);
    #pragma unroll
    for (int c = 0; c < 8; c++) {
        float4 o;
        o.x = acc[4*c+0] * inv; o.y = acc[4*c+1] * inv;
        o.z = acc[4*c+2] * inv; o.w = acc[4*c+3] * inv;
        optr4[2 * c + half] = o;
    }
}

// ---------------------------------------------------------------------------
// Launch
// ---------------------------------------------------------------------------
extern "C" void kernel_launch(void* const* d_in, const int* in_sizes, int n_in,
                              void* d_out, int out_size)
{
    const float* query = (const float*)d_in[0];
    const float* key   = (const float*)d_in[1];
    const float* value = (const float*)d_in[2];
    // d_in[3] = mask (deterministic causal tril) — implemented analytically
    const float* Wq = (const float*)d_in[4];
    const float* bq = (const float*)d_in[5];
    const float* Wk = (const float*)d_in[6];
    const float* bk = (const float*)d_in[7];
    const float* Wv = (const float*)d_in[8];
    const float* bv = (const float*)d_in[9];
    const float* Wo = (const float*)d_in[10];
    const float* bo = (const float*)d_in[11];
    float* out = (float*)d_out;

    float *gq, *gk, *gv, *gx;
    cudaGetSymbolAddress((void**)&gq, g_q);
    cudaGetSymbolAddress((void**)&gk, g_k);
    cudaGetSymbolAddress((void**)&gv, g_v);
    cudaGetSymbolAddress((void**)&gx, g_x);

    const dim3 ggrid(DD / 64, MROWS / 64);   // (8, 64)
    gemm_bias_kernel<<<ggrid, 256>>>(query, Wq, bq, gq, MROWS, DD, DD);
    gemm_bias_kernel<<<ggrid, 256>>>(key,   Wk, bk, gk, MROWS, DD, DD);
    gemm_bias_kernel<<<ggrid, 256>>>(value, Wv, bv, gv, MROWS, DD, DD);

    const dim3 agrid(SS / BQ, BB * HH);      // (32, 16)
    attn_kernel<<<agrid, 128>>>(gq, gk, gv, gx);

    gemm_bias_kernel<<<ggrid, 256>>>(gx, Wo, bo, out, MROWS, DD, DD);
}

// round 13
// speedup vs baseline: 1.6047x; 1.2533x over previous
#include <cuda_runtime.h>
#include <cuda_bf16.h>
#include <cstdint>

#define BB 2
#define SS 2048
#define DD 512
#define HH 8
#define DKK 64
#define MROWS (BB*SS)   // 4096

// ---------------------------------------------------------------------------
// Scratch (static device globals — no allocation allowed)
// ---------------------------------------------------------------------------
__device__ float g_q[MROWS * DD];
__device__ float g_k[MROWS * DD];
__device__ float g_v[MROWS * DD];
__device__ float g_x[MROWS * DD];
__device__ __nv_bfloat16 g_ahi[MROWS * DD];
__device__ __nv_bfloat16 g_alo[MROWS * DD];
__device__ __nv_bfloat16 g_whi[DD * DD];
__device__ __nv_bfloat16 g_wlo[DD * DD];

// ---------------------------------------------------------------------------
// Helpers (family-safe PTX only: ldmatrix / mma.sync / cp.async)
// ---------------------------------------------------------------------------
__device__ __forceinline__ uint32_t s2u(const void* p) {
    return (uint32_t)__cvta_generic_to_shared(p);
}

__device__ __forceinline__ void ldm_x4(uint32_t* r, uint32_t addr) {
    asm volatile("ldmatrix.sync.aligned.m8n8.x4.shared.b16 {%0,%1,%2,%3}, [%4];"
                 : "=r"(r[0]), "=r"(r[1]), "=r"(r[2]), "=r"(r[3]) : "r"(addr));
}

__device__ __forceinline__ void mma16816(float* c, const uint32_t* a,
                                         uint32_t b0, uint32_t b1) {
    asm volatile(
        "mma.sync.aligned.m16n8k16.row.col.f32.bf16.bf16.f32 "
        "{%0,%1,%2,%3}, {%4,%5,%6,%7}, {%8,%9}, {%0,%1,%2,%3};"
        : "+f"(c[0]), "+f"(c[1]), "+f"(c[2]), "+f"(c[3])
        : "r"(a[0]), "r"(a[1]), "r"(a[2]), "r"(a[3]), "r"(b0), "r"(b1));
}

__device__ __forceinline__ void cpa16(void* s, const void* g) {
    uint32_t saddr = s2u(s);
    asm volatile("cp.async.cg.shared.global [%0], [%1], 16;\n"
                 :: "r"(saddr), "l"(g) : "memory");
}
__device__ __forceinline__ void cpa_commit() {
    asm volatile("cp.async.commit_group;\n" ::: "memory");
}
template <int N>
__device__ __forceinline__ void cpa_wait() {
    asm volatile("cp.async.wait_group %0;\n" :: "n"(N) : "memory");
}

// ---------------------------------------------------------------------------
// fp32 -> bf16 (hi, lo) split, vectorized x4
// ---------------------------------------------------------------------------
__global__ __launch_bounds__(256) void split_bf16_kernel(
    const float4* __restrict__ x, uint2* __restrict__ hi, uint2* __restrict__ lo, int n4)
{
    int i = blockIdx.x * 256 + threadIdx.x;
    if (i >= n4) return;
    float4 v = x[i];
    __nv_bfloat16 hx = __float2bfloat16(v.x), hy = __float2bfloat16(v.y);
    __nv_bfloat16 hz = __float2bfloat16(v.z), hw = __float2bfloat16(v.w);
    __nv_bfloat16 lx = __float2bfloat16(v.x - __bfloat162float(hx));
    __nv_bfloat16 ly = __float2bfloat16(v.y - __bfloat162float(hy));
    __nv_bfloat16 lz = __float2bfloat16(v.z - __bfloat162float(hz));
    __nv_bfloat16 lw = __float2bfloat16(v.w - __bfloat162float(hw));
    uint2 H, L;
    H.x = ((uint32_t)__bfloat16_as_ushort(hy) << 16) | __bfloat16_as_ushort(hx);
    H.y = ((uint32_t)__bfloat16_as_ushort(hw) << 16) | __bfloat16_as_ushort(hz);
    L.x = ((uint32_t)__bfloat16_as_ushort(ly) << 16) | __bfloat16_as_ushort(lx);
    L.y = ((uint32_t)__bfloat16_as_ushort(lw) << 16) | __bfloat16_as_ushort(lz);
    hi[i] = H; lo[i] = L;
}

// ---------------------------------------------------------------------------
// Tensor-core GEMM via mma.sync (HMMA, family-safe): C = A @ W^T + bias,
// fp32-accurate via bf16 hi/lo 3-pass (Ah*Wh + Ah*Wl + Al*Wh).
// CTA tile 128(M)x64(N), K chunked by 64. 256 threads = 8 warps in 4(M)x2(N);
// each warp owns 32x32 = 2 m16-frags x 4 n8-frags.
// Smem: SW128-swizzled 128B rows -> conflict-free ldmatrix.
// ---------------------------------------------------------------------------
#define GM 128
#define GN 64
#define GK 64
#define OFF_AHI 0
#define OFF_ALO 16384
#define OFF_WHI 32768
#define OFF_WLO 40960
#define SMEM_GEMM 49152

__global__ __launch_bounds__(256) void mma_gemm_kernel(
    const __nv_bfloat16* __restrict__ Ahi, const __nv_bfloat16* __restrict__ Alo,
    const __nv_bfloat16* __restrict__ Whi, const __nv_bfloat16* __restrict__ Wlo,
    const float* __restrict__ bias, float* __restrict__ C,
    int M, int N, int K)
{
    extern __shared__ char smem[];
    const uint32_t smem_base = s2u(smem);

    const int tid  = threadIdx.x;
    const int lane = tid & 31;
    const int wid  = tid >> 5;
    const int mw   = wid & 3;    // 4 m-blocks of 32 rows
    const int nw   = wid >> 2;   // 2 n-blocks of 32 cols

    const int m0 = blockIdx.y * GM;
    const int n0 = blockIdx.x * GN;

    float acc[2][4][4] = {};     // [m16][n8][frag]

    const int lr = lane & 15;    // row within 16-row ldmatrix tile
    const int kh = lane >> 4;    // k-half (0: k0-7, 1: k8-15)

    for (int ci = 0; ci < K / GK; ci++) {
        const int kc = ci * GK;

        // --- stage A (128 rows x 128B) and W (64 rows x 128B), SW128 ---
        #pragma unroll
        for (int i = tid; i < 128 * 8; i += 256) {
            const int r = i >> 3, c = i & 7;
            const uint32_t sw = r * 128 + ((c ^ (r & 7)) << 4);
            *(uint4*)(smem + OFF_AHI + sw) = ((const uint4*)&Ahi[(size_t)(m0 + r) * K + kc])[c];
            *(uint4*)(smem + OFF_ALO + sw) = ((const uint4*)&Alo[(size_t)(m0 + r) * K + kc])[c];
        }
        #pragma unroll
        for (int i = tid; i < 64 * 8; i += 256) {
            const int r = i >> 3, c = i & 7;
            const uint32_t sw = r * 128 + ((c ^ (r & 7)) << 4);
            *(uint4*)(smem + OFF_WHI + sw) = ((const uint4*)&Whi[(size_t)(n0 + r) * K + kc])[c];
            *(uint4*)(smem + OFF_WLO + sw) = ((const uint4*)&Wlo[(size_t)(n0 + r) * K + kc])[c];
        }
        __syncthreads();

        #pragma unroll
        for (int j = 0; j < 4; j++) {            // k16 steps within the 64-K tile
            const int c = 2 * j + kh;            // 16B chunk index (k direction)

            uint32_t ah[2][4], al[2][4];
            #pragma unroll
            for (int i = 0; i < 2; i++) {        // m16 tiles
                const int row = mw * 32 + i * 16 + lr;
                const uint32_t sw = row * 128 + (((c) ^ (row & 7)) << 4);
                ldm_x4(ah[i], smem_base + OFF_AHI + sw);
                ldm_x4(al[i], smem_base + OFF_ALO + sw);
            }
            uint32_t bh[2][4], bl[2][4];
            #pragma unroll
            for (int jj = 0; jj < 2; jj++) {     // n16 tiles
                const int row = nw * 32 + jj * 16 + lr;
                const uint32_t sw = row * 128 + (((c) ^ (row & 7)) << 4);
                ldm_x4(bh[jj], smem_base + OFF_WHI + sw);
                ldm_x4(bl[jj], smem_base + OFF_WLO + sw);
            }

            // regs of a W x4 load: 0=(n0-7,klo) 1=(n8-15,klo) 2=(n0-7,khi) 3=(n8-15,khi)
            // n8 frag g (within n16 tile jj, h2 = g&1): {reg[h2], reg[h2+2]}
            #pragma unroll
            for (int i = 0; i < 2; i++) {
                #pragma unroll
                for (int g = 0; g < 4; g++) {
                    const int jj = g >> 1, h2 = g & 1;
                    mma16816(acc[i][g], ah[i], bh[jj][h2], bh[jj][h2 + 2]);  // hi*hi
                    mma16816(acc[i][g], ah[i], bl[jj][h2], bl[jj][h2 + 2]);  // hi*lo
                    mma16816(acc[i][g], al[i], bh[jj][h2], bh[jj][h2 + 2]);  // lo*hi
                }
            }
        }
        __syncthreads();
    }

    // --- epilogue: c0,c1 -> (row t/4, col 2*(t%4)..+1); c2,c3 -> row+8 ---
    #pragma unroll
    for (int i = 0; i < 2; i++) {
        const int r0 = m0 + mw * 32 + i * 16 + (lane >> 2);
        #pragma unroll
        for (int g = 0; g < 4; g++) {
            const int cn = n0 + nw * 32 + g * 8 + (lane & 3) * 2;
            const float2 bv = *(const float2*)&bias[cn];
            float2 o0, o1;
            o0.x = acc[i][g][0] + bv.x; o0.y = acc[i][g][1] + bv.y;
            o1.x = acc[i][g][2] + bv.x; o1.y = acc[i][g][3] + bv.y;
            *(float2*)&C[(size_t)r0 * N + cn]       = o0;
            *(float2*)&C[(size_t)(r0 + 8) * N + cn] = o1;
        }
    }
}

// ---------------------------------------------------------------------------
// Flash attention (causal), fp32, 2-lanes-per-row split + cp.async
// double-buffered K/V tiles.
// ---------------------------------------------------------------------------
#define BN 32
#define BQ 64

__global__ __launch_bounds__(128, 3) void attn_kernel(
    const float* __restrict__ gq, const float* __restrict__ gk,
    const float* __restrict__ gv, float* __restrict__ gx)
{
    __shared__ float Ks[2][BN][DKK];   // 2 x 8 KB
    __shared__ float Vs[2][BN][DKK];   // 2 x 8 KB

    const int tid  = threadIdx.x;
    const int lane = tid & 31;
    const int warp = tid >> 5;
    const int row  = warp * 16 + (lane & 15);
    const int half = lane >> 4;

    const int qt = blockIdx.x;
    const int bh = blockIdx.y;
    const int b  = bh / HH;
    const int h  = bh % HH;
    const int q_glob = qt * BQ + row;

    const float scale = 0.125f;   // 1/sqrt(64)

    const float4* qptr4 = (const float4*)(gq + ((size_t)b * SS + q_glob) * DD + h * DKK);
    float q[32];
    #pragma unroll
    for (int c = 0; c < 8; c++) {
        float4 v = qptr4[2 * c + half];
        q[4*c+0] = v.x * scale; q[4*c+1] = v.y * scale;
        q[4*c+2] = v.z * scale; q[4*c+3] = v.w * scale;
    }

    float acc[32];
    #pragma unroll
    for (int d = 0; d < 32; d++) acc[d] = 0.f;
    float mrow = -1e30f, l = 0.f;

    const float* kbase = gk + (size_t)b * SS * DD + h * DKK;
    const float* vbase = gv + (size_t)b * SS * DD + h * DKK;

    const int nkt = (qt + 1) * (BQ / BN);   // causal: key tiles needed

    // prefetch tile 0 into buffer 0
    {
        #pragma unroll
        for (int i = tid; i < BN * 16; i += 128) {
            const int r = i >> 4, c = i & 15;
            cpa16(&Ks[0][r][c * 4], &kbase[(size_t)r * DD + c * 4]);
            cpa16(&Vs[0][r][c * 4], &vbase[(size_t)r * DD + c * 4]);
        }
        cpa_commit();
    }

    for (int kt = 0; kt < nkt; kt++) {
        const int cur = kt & 1;
        if (kt + 1 < nkt) {
            const int k1 = (kt + 1) * BN;
            #pragma unroll
            for (int i = tid; i < BN * 16; i += 128) {
                const int r = i >> 4, c = i & 15;
                cpa16(&Ks[cur ^ 1][r][c * 4], &kbase[(size_t)(k1 + r) * DD + c * 4]);
                cpa16(&Vs[cur ^ 1][r][c * 4], &vbase[(size_t)(k1 + r) * DD + c * 4]);
            }
            cpa_commit();
            cpa_wait<1>();
        } else {
            cpa_wait<0>();
        }
        __syncthreads();

        const int k0 = kt * BN;
        const float (*K_)[DKK] = Ks[cur];
        const float (*V_)[DKK] = Vs[cur];

        float s[BN];
        #pragma unroll
        for (int kk = 0; kk < BN; kk++) {
            float a0 = 0.f, a1 = 0.f, a2 = 0.f, a3 = 0.f;
            #pragma unroll
            for (int c = 0; c < 8; c++) {
                float4 kv = ((const float4*)K_[kk])[2 * c + half];
                a0 += q[4*c+0] * kv.x; a1 += q[4*c+1] * kv.y;
                a2 += q[4*c+2] * kv.z; a3 += q[4*c+3] * kv.w;
            }
            s[kk] = (a0 + a1) + (a2 + a3);
        }
        #pragma unroll
        for (int kk = 0; kk < BN; kk++)
            s[kk] += __shfl_xor_sync(0xffffffffu, s[kk], 16);

        if (k0 + BN - 1 > q_glob) {
            #pragma unroll
            for (int kk = 0; kk < BN; kk++)
                if (k0 + kk > q_glob) s[kk] = -1e30f;
        }

        float mnew = mrow;
        #pragma unroll
        for (int kk = 0; kk < BN; kk++) mnew = fmaxf(mnew, s[kk]);
        const float corr = __expf(mrow - mnew);
        mrow = mnew;
        l *= corr;
        #pragma unroll
        for (int d = 0; d < 32; d++) acc[d] *= corr;

        #pragma unroll
        for (int kk = 0; kk < BN; kk++) {
            s[kk] = __expf(s[kk] - mnew);
            l += s[kk];
        }

        #pragma unroll
        for (int kk = 0; kk < BN; kk++) {
            const float p = s[kk];
            #pragma unroll
            for (int c = 0; c < 8; c++) {
                float4 vv = ((const float4*)V_[kk])[2 * c + half];
                acc[4*c+0] += p * vv.x; acc[4*c+1] += p * vv.y;
                acc[4*c+2] += p * vv.z; acc[4*c+3] += p * vv.w;
            }
        }
        __syncthreads();   // all warps done with buf[cur] before it is refilled
    }

    const float inv = 1.f / l;
    float4* optr4 = (float4*)(gx + ((size_t)b * SS + q_glob) * DD + h * DKK);
    #pragma unroll
    for (int c = 0; c < 8; c++) {
        float4 o;
        o.x = acc[4*c+0] * inv; o.y = acc[4*c+1] * inv;
        o.z = acc[4*c+2] * inv; o.w = acc[4*c+3] * inv;
        optr4[2 * c + half] = o;
    }
}

// ---------------------------------------------------------------------------
// Launch
// ---------------------------------------------------------------------------
extern "C" void kernel_launch(void* const* d_in, const int* in_sizes, int n_in,
                              void* d_out, int out_size)
{
    const float* query = (const float*)d_in[0];
    const float* key   = (const float*)d_in[1];
    const float* value = (const float*)d_in[2];
    // d_in[3] = mask (deterministic causal tril) — implemented analytically
    const float* Wq = (const float*)d_in[4];
    const float* bq = (const float*)d_in[5];
    const float* Wk = (const float*)d_in[6];
    const float* bk = (const float*)d_in[7];
    const float* Wv = (const float*)d_in[8];
    const float* bv = (const float*)d_in[9];
    const float* Wo = (const float*)d_in[10];
    const float* bo = (const float*)d_in[11];
    float* out = (float*)d_out;

    float *gq, *gk, *gv, *gx;
    __nv_bfloat16 *ahi, *alo, *whi, *wlo;
    cudaGetSymbolAddress((void**)&gq, g_q);
    cudaGetSymbolAddress((void**)&gk, g_k);
    cudaGetSymbolAddress((void**)&gv, g_v);
    cudaGetSymbolAddress((void**)&gx, g_x);
    cudaGetSymbolAddress((void**)&ahi, g_ahi);
    cudaGetSymbolAddress((void**)&alo, g_alo);
    cudaGetSymbolAddress((void**)&whi, g_whi);
    cudaGetSymbolAddress((void**)&wlo, g_wlo);

    const int NA4 = MROWS * DD / 4;   // 524288
    const int NW4 = DD * DD / 4;      // 65536
    const dim3 ggrid(DD / GN, MROWS / GM);   // (8, 32)

    // Q projection
    split_bf16_kernel<<<NA4 / 256, 256>>>((const float4*)query, (uint2*)ahi, (uint2*)alo, NA4);
    split_bf16_kernel<<<NW4 / 256, 256>>>((const float4*)Wq, (uint2*)whi, (uint2*)wlo, NW4);
    mma_gemm_kernel<<<ggrid, 256, SMEM_GEMM>>>(ahi, alo, whi, wlo, bq, gq, MROWS, DD, DD);
    // K projection
    split_bf16_kernel<<<NA4 / 256, 256>>>((const float4*)key, (uint2*)ahi, (uint2*)alo, NA4);
    split_bf16_kernel<<<NW4 / 256, 256>>>((const float4*)Wk, (uint2*)whi, (uint2*)wlo, NW4);
    mma_gemm_kernel<<<ggrid, 256, SMEM_GEMM>>>(ahi, alo, whi, wlo, bk, gk, MROWS, DD, DD);
    // V projection
    split_bf16_kernel<<<NA4 / 256, 256>>>((const float4*)value, (uint2*)ahi, (uint2*)alo, NA4);
    split_bf16_kernel<<<NW4 / 256, 256>>>((const float4*)Wv, (uint2*)whi, (uint2*)wlo, NW4);
    mma_gemm_kernel<<<ggrid, 256, SMEM_GEMM>>>(ahi, alo, whi, wlo, bv, gv, MROWS, DD, DD);

    // attention
    const dim3 agrid(SS / BQ, BB * HH);   // (32, 16)
    attn_kernel<<<agrid, 128>>>(gq, gk, gv, gx);

    // output projection
    split_bf16_kernel<<<NA4 / 256, 256>>>((const float4*)gx, (uint2*)ahi, (uint2*)alo, NA4);
    split_bf16_kernel<<<NW4 / 256, 256>>>((const float4*)Wo, (uint2*)whi, (uint2*)wlo, NW4);
    mma_gemm_kernel<<<ggrid, 256, SMEM_GEMM>>>(ahi, alo, whi, wlo, bo, out, MROWS, DD, DD);
}

// round 17
// speedup vs baseline: 3.6383x; 2.2673x over previous
#include <cuda_runtime.h>
#include <cuda_bf16.h>
#include <cstdint>

#define BB 2
#define SS 2048
#define DD 512
#define HH 8
#define DKK 64
#define MROWS (BB*SS)   // 4096

// ---------------------------------------------------------------------------
// Scratch (static device globals — no allocation allowed)
// ---------------------------------------------------------------------------
__device__ float g_x[MROWS * DD];                 // attention output (fp32)
__device__ __nv_bfloat16 g_ahi[MROWS * DD];       // GEMM A staging
__device__ __nv_bfloat16 g_alo[MROWS * DD];
__device__ __nv_bfloat16 g_whi[DD * DD];
__device__ __nv_bfloat16 g_wlo[DD * DD];
__device__ __nv_bfloat16 g_qhi[MROWS * DD];       // projected Q/K/V, bf16 hi/lo
__device__ __nv_bfloat16 g_qlo[MROWS * DD];
__device__ __nv_bfloat16 g_khi[MROWS * DD];
__device__ __nv_bfloat16 g_klo[MROWS * DD];
__device__ __nv_bfloat16 g_vhi[MROWS * DD];
__device__ __nv_bfloat16 g_vlo[MROWS * DD];

// ---------------------------------------------------------------------------
// Helpers (family-safe PTX only: ldmatrix / mma.sync / cp.async)
// ---------------------------------------------------------------------------
__device__ __forceinline__ uint32_t s2u(const void* p) {
    return (uint32_t)__cvta_generic_to_shared(p);
}

__device__ __forceinline__ void ldm_x4(uint32_t* r, uint32_t addr) {
    asm volatile("ldmatrix.sync.aligned.m8n8.x4.shared.b16 {%0,%1,%2,%3}, [%4];"
                 : "=r"(r[0]), "=r"(r[1]), "=r"(r[2]), "=r"(r[3]) : "r"(addr));
}
__device__ __forceinline__ void ldm_x4_t(uint32_t* r, uint32_t addr) {
    asm volatile("ldmatrix.sync.aligned.m8n8.x4.trans.shared.b16 {%0,%1,%2,%3}, [%4];"
                 : "=r"(r[0]), "=r"(r[1]), "=r"(r[2]), "=r"(r[3]) : "r"(addr));
}

__device__ __forceinline__ void mma16816(float* c, const uint32_t* a,
                                         uint32_t b0, uint32_t b1) {
    asm volatile(
        "mma.sync.aligned.m16n8k16.row.col.f32.bf16.bf16.f32 "
        "{%0,%1,%2,%3}, {%4,%5,%6,%7}, {%8,%9}, {%0,%1,%2,%3};"
        : "+f"(c[0]), "+f"(c[1]), "+f"(c[2]), "+f"(c[3])
        : "r"(a[0]), "r"(a[1]), "r"(a[2]), "r"(a[3]), "r"(b0), "r"(b1));
}

__device__ __forceinline__ void cpa16(void* s, const void* g) {
    uint32_t saddr = s2u(s);
    asm volatile("cp.async.cg.shared.global [%0], [%1], 16;\n"
                 :: "r"(saddr), "l"(g) : "memory");
}
__device__ __forceinline__ void cpa_commit() {
    asm volatile("cp.async.commit_group;\n" ::: "memory");
}
template <int N>
__device__ __forceinline__ void cpa_wait() {
    asm volatile("cp.async.wait_group %0;\n" :: "n"(N) : "memory");
}

// pack two floats into bf16 hi pair + bf16 lo-residual pair
__device__ __forceinline__ void split2(float x, float y, uint32_t& h, uint32_t& l) {
    __nv_bfloat16 hx = __float2bfloat16(x), hy = __float2bfloat16(y);
    __nv_bfloat16 lx = __float2bfloat16(x - __bfloat162float(hx));
    __nv_bfloat16 ly = __float2bfloat16(y - __bfloat162float(hy));
    h = ((uint32_t)__bfloat16_as_ushort(hy) << 16) | __bfloat16_as_ushort(hx);
    l = ((uint32_t)__bfloat16_as_ushort(ly) << 16) | __bfloat16_as_ushort(lx);
}

// ---------------------------------------------------------------------------
// fp32 -> bf16 (hi, lo) split, vectorized x4
// ---------------------------------------------------------------------------
__global__ __launch_bounds__(256) void split_bf16_kernel(
    const float4* __restrict__ x, uint2* __restrict__ hi, uint2* __restrict__ lo, int n4)
{
    int i = blockIdx.x * 256 + threadIdx.x;
    if (i >= n4) return;
    float4 v = x[i];
    uint2 H, L;
    split2(v.x, v.y, H.x, L.x);
    split2(v.z, v.w, H.y, L.y);
    hi[i] = H; lo[i] = L;
}

// ---------------------------------------------------------------------------
// Tensor-core GEMM (HMMA): C = A @ W^T + bias, bf16 hi/lo 3-pass.
// CTA tile 128x64, K chunked by 64. 256 threads = 8 warps 4(M)x2(N).
// Epilogue: fp32 C (Chi==null) or bf16 hi/lo pair with scale (for Q/K/V).
// ---------------------------------------------------------------------------
#define GM 128
#define GN 64
#define GK 64
#define OFF_AHI 0
#define OFF_ALO 16384
#define OFF_WHI 32768
#define OFF_WLO 40960
#define SMEM_GEMM 49152

__global__ __launch_bounds__(256) void mma_gemm_kernel(
    const __nv_bfloat16* __restrict__ Ahi, const __nv_bfloat16* __restrict__ Alo,
    const __nv_bfloat16* __restrict__ Whi, const __nv_bfloat16* __restrict__ Wlo,
    const float* __restrict__ bias, float* __restrict__ C,
    __nv_bfloat16* __restrict__ Chi, __nv_bfloat16* __restrict__ Clo,
    float scale, int M, int N, int K)
{
    extern __shared__ char smem[];
    const uint32_t smem_base = s2u(smem);

    const int tid  = threadIdx.x;
    const int lane = tid & 31;
    const int wid  = tid >> 5;
    const int mw   = wid & 3;
    const int nw   = wid >> 2;

    const int m0 = blockIdx.y * GM;
    const int n0 = blockIdx.x * GN;

    float acc[2][4][4] = {};

    const int lr = lane & 15;
    const int kh = lane >> 4;

    for (int ci = 0; ci < K / GK; ci++) {
        const int kc = ci * GK;

        #pragma unroll
        for (int i = tid; i < 128 * 8; i += 256) {
            const int r = i >> 3, c = i & 7;
            const uint32_t sw = r * 128 + ((c ^ (r & 7)) << 4);
            *(uint4*)(smem + OFF_AHI + sw) = ((const uint4*)&Ahi[(size_t)(m0 + r) * K + kc])[c];
            *(uint4*)(smem + OFF_ALO + sw) = ((const uint4*)&Alo[(size_t)(m0 + r) * K + kc])[c];
        }
        #pragma unroll
        for (int i = tid; i < 64 * 8; i += 256) {
            const int r = i >> 3, c = i & 7;
            const uint32_t sw = r * 128 + ((c ^ (r & 7)) << 4);
            *(uint4*)(smem + OFF_WHI + sw) = ((const uint4*)&Whi[(size_t)(n0 + r) * K + kc])[c];
            *(uint4*)(smem + OFF_WLO + sw) = ((const uint4*)&Wlo[(size_t)(n0 + r) * K + kc])[c];
        }
        __syncthreads();

        #pragma unroll
        for (int j = 0; j < 4; j++) {
            const int c = 2 * j + kh;

            uint32_t ah[2][4], al[2][4];
            #pragma unroll
            for (int i = 0; i < 2; i++) {
                const int row = mw * 32 + i * 16 + lr;
                const uint32_t sw = row * 128 + ((c ^ (row & 7)) << 4);
                ldm_x4(ah[i], smem_base + OFF_AHI + sw);
                ldm_x4(al[i], smem_base + OFF_ALO + sw);
            }
            uint32_t bh[2][4], bl[2][4];
            #pragma unroll
            for (int jj = 0; jj < 2; jj++) {
                const int row = nw * 32 + jj * 16 + lr;
                const uint32_t sw = row * 128 + ((c ^ (row & 7)) << 4);
                ldm_x4(bh[jj], smem_base + OFF_WHI + sw);
                ldm_x4(bl[jj], smem_base + OFF_WLO + sw);
            }

            #pragma unroll
            for (int i = 0; i < 2; i++) {
                #pragma unroll
                for (int g = 0; g < 4; g++) {
                    const int jj = g >> 1, h2 = g & 1;
                    mma16816(acc[i][g], ah[i], bh[jj][h2], bh[jj][h2 + 2]);
                    mma16816(acc[i][g], ah[i], bl[jj][h2], bl[jj][h2 + 2]);
                    mma16816(acc[i][g], al[i], bh[jj][h2], bh[jj][h2 + 2]);
                }
            }
        }
        __syncthreads();
    }

    #pragma unroll
    for (int i = 0; i < 2; i++) {
        const int r0 = m0 + mw * 32 + i * 16 + (lane >> 2);
        #pragma unroll
        for (int g = 0; g < 4; g++) {
            const int cn = n0 + nw * 32 + g * 8 + (lane & 3) * 2;
            const float2 bv = *(const float2*)&bias[cn];
            float x0 = (acc[i][g][0] + bv.x) * scale;
            float y0 = (acc[i][g][1] + bv.y) * scale;
            float x1 = (acc[i][g][2] + bv.x) * scale;
            float y1 = (acc[i][g][3] + bv.y) * scale;
            if (Chi) {
                uint32_t h0, l0, h1, l1;
                split2(x0, y0, h0, l0);
                split2(x1, y1, h1, l1);
                const size_t e0 = ((size_t)r0 * N + cn) >> 1;
                const size_t e1 = ((size_t)(r0 + 8) * N + cn) >> 1;
                ((uint32_t*)Chi)[e0] = h0; ((uint32_t*)Clo)[e0] = l0;
                ((uint32_t*)Chi)[e1] = h1; ((uint32_t*)Clo)[e1] = l1;
            } else {
                *(float2*)&C[(size_t)r0 * N + cn]       = make_float2(x0, y0);
                *(float2*)&C[(size_t)(r0 + 8) * N + cn] = make_float2(x1, y1);
            }
        }
    }
}

// ---------------------------------------------------------------------------
// Tensor-core flash attention (causal). Block: 64 q rows, 4 warps (16 rows
// each). Key tiles of 64, K/V bf16 hi/lo cp.async double-buffered in SW128
// smem. QK^T and PV on mma.sync bf16 with hi/lo 3-pass; softmax fp32 in
// C-fragments; P reuses C-frag->A-frag layout identity. Q is pre-scaled.
// ---------------------------------------------------------------------------
#define A_KH 0
#define A_KL 8192
#define A_VH 16384
#define A_VL 24576
#define A_BUF 32768
#define SMEM_ATTN 65536

__device__ __forceinline__ void stage_tile(
    char* smem, int bufsel, int tid,
    const __nv_bfloat16* kh, const __nv_bfloat16* kl,
    const __nv_bfloat16* vh, const __nv_bfloat16* vl, size_t rowoff)
{
    char* base = smem + bufsel * A_BUF;
    #pragma unroll
    for (int i = tid; i < 512; i += 128) {
        const int key = i >> 3, c = i & 7;
        const uint32_t dst = key * 128 + ((c ^ (key & 7)) << 4);
        const size_t go = rowoff + (size_t)key * DD;
        cpa16(base + A_KH + dst, (const char*)(kh + go) + c * 16);
        cpa16(base + A_KL + dst, (const char*)(kl + go) + c * 16);
        cpa16(base + A_VH + dst, (const char*)(vh + go) + c * 16);
        cpa16(base + A_VL + dst, (const char*)(vl + go) + c * 16);
    }
}

__global__ __launch_bounds__(128, 3) void attn_mma_kernel(
    const __nv_bfloat16* __restrict__ qhi, const __nv_bfloat16* __restrict__ qlo,
    const __nv_bfloat16* __restrict__ khi, const __nv_bfloat16* __restrict__ klo,
    const __nv_bfloat16* __restrict__ vhi, const __nv_bfloat16* __restrict__ vlo,
    float* __restrict__ gx)
{
    extern __shared__ char smem[];
    const uint32_t sbase = s2u(smem);

    const int tid  = threadIdx.x;
    const int lane = tid & 31;
    const int w    = tid >> 5;
    const int g    = lane >> 2;     // row within 8
    const int t    = lane & 3;      // col pair index
    const int lr   = lane & 15;
    const int lkh  = lane >> 4;

    const int qt = blockIdx.x;
    const int bh = blockIdx.y;
    const int b  = bh / HH;
    const int h  = bh % HH;

    // --- Q A-fragments via direct LDG (values pre-scaled by 1/8) ---
    uint32_t qh[4][4], ql[4][4];
    {
        const size_t r0 = ((size_t)b * SS + qt * 64 + w * 16 + g) * DD + h * DKK;
        const size_t r8 = r0 + 8 * DD;
        #pragma unroll
        for (int ks = 0; ks < 4; ks++) {
            const int d0 = 16 * ks + 2 * t;
            qh[ks][0] = *(const uint32_t*)&qhi[r0 + d0];
            qh[ks][1] = *(const uint32_t*)&qhi[r8 + d0];
            qh[ks][2] = *(const uint32_t*)&qhi[r0 + d0 + 8];
            qh[ks][3] = *(const uint32_t*)&qhi[r8 + d0 + 8];
            ql[ks][0] = *(const uint32_t*)&qlo[r0 + d0];
            ql[ks][1] = *(const uint32_t*)&qlo[r8 + d0];
            ql[ks][2] = *(const uint32_t*)&qlo[r0 + d0 + 8];
            ql[ks][3] = *(const uint32_t*)&qlo[r8 + d0 + 8];
        }
    }

    float o[8][4] = {};
    float m1 = -1e30f, m2 = -1e30f, l1 = 0.f, l2 = 0.f;

    const size_t kvbase = (size_t)b * SS * DD + h * DKK;

    const int nkt = qt + 1;
    stage_tile(smem, 0, tid, khi, klo, vhi, vlo, kvbase);
    cpa_commit();

    for (int kt = 0; kt < nkt; kt++) {
        const int cur = kt & 1;
        if (kt + 1 < nkt) {
            stage_tile(smem, cur ^ 1, tid, khi, klo, vhi, vlo,
                       kvbase + (size_t)(kt + 1) * 64 * DD);
            cpa_commit();
            cpa_wait<1>();
        } else {
            cpa_wait<0>();
        }
        __syncthreads();

        const uint32_t KH = sbase + cur * A_BUF + A_KH;
        const uint32_t KL = sbase + cur * A_BUF + A_KL;
        const uint32_t VH = sbase + cur * A_BUF + A_VH;
        const uint32_t VL = sbase + cur * A_BUF + A_VL;

        // --- S = Q K^T (3-pass) ---
        float s[8][4] = {};
        #pragma unroll
        for (int ks = 0; ks < 4; ks++) {
            #pragma unroll
            for (int kg = 0; kg < 4; kg++) {
                uint32_t kh4[4], kl4[4];
                const int row = kg * 16 + lr;
                const int c   = 2 * ks + lkh;
                const uint32_t sw = row * 128 + ((c ^ (row & 7)) << 4);
                ldm_x4(kh4, KH + sw);
                ldm_x4(kl4, KL + sw);
                #pragma unroll
                for (int h2 = 0; h2 < 2; h2++) {
                    const int f = kg * 2 + h2;
                    mma16816(s[f], qh[ks], kh4[h2], kh4[h2 + 2]);
                    mma16816(s[f], qh[ks], kl4[h2], kl4[h2 + 2]);
                    mma16816(s[f], ql[ks], kh4[h2], kh4[h2 + 2]);
                }
            }
        }

        // --- causal mask (diagonal tile only; same tile offset q & k) ---
        if (kt == qt) {
            const int r1k = w * 16 + g;
            const int r2k = r1k + 8;
            #pragma unroll
            for (int f = 0; f < 8; f++) {
                const int c0 = f * 8 + 2 * t, c1 = c0 + 1;
                if (c0 > r1k) s[f][0] = -1e30f;
                if (c1 > r1k) s[f][1] = -1e30f;
                if (c0 > r2k) s[f][2] = -1e30f;
                if (c1 > r2k) s[f][3] = -1e30f;
            }
        }

        // --- online softmax (rows r1 = .., r2 = r1+8) ---
        float mx1 = -1e30f, mx2 = -1e30f;
        #pragma unroll
        for (int f = 0; f < 8; f++) {
            mx1 = fmaxf(mx1, fmaxf(s[f][0], s[f][1]));
            mx2 = fmaxf(mx2, fmaxf(s[f][2], s[f][3]));
        }
        mx1 = fmaxf(mx1, __shfl_xor_sync(0xffffffffu, mx1, 1));
        mx1 = fmaxf(mx1, __shfl_xor_sync(0xffffffffu, mx1, 2));
        mx2 = fmaxf(mx2, __shfl_xor_sync(0xffffffffu, mx2, 1));
        mx2 = fmaxf(mx2, __shfl_xor_sync(0xffffffffu, mx2, 2));

        const float nm1 = fmaxf(m1, mx1);
        const float nm2 = fmaxf(m2, mx2);
        const float cr1 = __expf(m1 - nm1);
        const float cr2 = __expf(m2 - nm2);
        m1 = nm1; m2 = nm2;
        l1 *= cr1; l2 *= cr2;
        #pragma unroll
        for (int f = 0; f < 8; f++) {
            o[f][0] *= cr1; o[f][1] *= cr1;
            o[f][2] *= cr2; o[f][3] *= cr2;
        }

        float rs1 = 0.f, rs2 = 0.f;
        #pragma unroll
        for (int f = 0; f < 8; f++) {
            s[f][0] = __expf(s[f][0] - nm1);
            s[f][1] = __expf(s[f][1] - nm1);
            s[f][2] = __expf(s[f][2] - nm2);
            s[f][3] = __expf(s[f][3] - nm2);
            rs1 += s[f][0] + s[f][1];
            rs2 += s[f][2] + s[f][3];
        }
        rs1 += __shfl_xor_sync(0xffffffffu, rs1, 1);
        rs1 += __shfl_xor_sync(0xffffffffu, rs1, 2);
        rs2 += __shfl_xor_sync(0xffffffffu, rs2, 1);
        rs2 += __shfl_xor_sync(0xffffffffu, rs2, 2);
        l1 += rs1; l2 += rs2;

        // --- O += P V (3-pass); P A-frags via C->A layout identity ---
        #pragma unroll
        for (int ks = 0; ks < 4; ks++) {
            uint32_t pah[4], pal[4];
            split2(s[2*ks][0],   s[2*ks][1],   pah[0], pal[0]);
            split2(s[2*ks][2],   s[2*ks][3],   pah[1], pal[1]);
            split2(s[2*ks+1][0], s[2*ks+1][1], pah[2], pal[2]);
            split2(s[2*ks+1][2], s[2*ks+1][3], pah[3], pal[3]);
            #pragma unroll
            for (int u = 0; u < 4; u++) {
                uint32_t vh4[4], vl4[4];
                const int row = ks * 16 + lr;
                const int c   = 2 * u + lkh;
                const uint32_t sw = row * 128 + ((c ^ (row & 7)) << 4);
                ldm_x4_t(vh4, VH + sw);
                ldm_x4_t(vl4, VL + sw);
                #pragma unroll
                for (int half = 0; half < 2; half++) {
                    const int f = 2 * u + half;
                    mma16816(o[f], pah, vh4[2*half], vh4[2*half+1]);
                    mma16816(o[f], pah, vl4[2*half], vl4[2*half+1]);
                    mma16816(o[f], pal, vh4[2*half], vh4[2*half+1]);
                }
            }
        }
        __syncthreads();   // all warps done with buf[cur] before refill
    }

    const float inv1 = 1.f / l1;
    const float inv2 = 1.f / l2;
    const size_t or1 = ((size_t)b * SS + qt * 64 + w * 16 + g) * DD + h * DKK;
    const size_t or2 = or1 + 8 * DD;
    #pragma unroll
    for (int f = 0; f < 8; f++) {
        const int cc = f * 8 + 2 * t;
        *(float2*)&gx[or1 + cc] = make_float2(o[f][0] * inv1, o[f][1] * inv1);
        *(float2*)&gx[or2 + cc] = make_float2(o[f][2] * inv2, o[f][3] * inv2);
    }
}

// ---------------------------------------------------------------------------
// Launch
// ---------------------------------------------------------------------------
extern "C" void kernel_launch(void* const* d_in, const int* in_sizes, int n_in,
                              void* d_out, int out_size)
{
    const float* query = (const float*)d_in[0];
    const float* key   = (const float*)d_in[1];
    const float* value = (const float*)d_in[2];
    // d_in[3] = mask (deterministic causal tril) — implemented analytically
    const float* Wq = (const float*)d_in[4];
    const float* bq = (const float*)d_in[5];
    const float* Wk = (const float*)d_in[6];
    const float* bk = (const float*)d_in[7];
    const float* Wv = (const float*)d_in[8];
    const float* bv = (const float*)d_in[9];
    const float* Wo = (const float*)d_in[10];
    const float* bo = (const float*)d_in[11];
    float* out = (float*)d_out;

    float* gx;
    __nv_bfloat16 *ahi, *alo, *whi, *wlo, *qhi, *qlo, *khi, *klo, *vhi, *vlo;
    cudaGetSymbolAddress((void**)&gx, g_x);
    cudaGetSymbolAddress((void**)&ahi, g_ahi);
    cudaGetSymbolAddress((void**)&alo, g_alo);
    cudaGetSymbolAddress((void**)&whi, g_whi);
    cudaGetSymbolAddress((void**)&wlo, g_wlo);
    cudaGetSymbolAddress((void**)&qhi, g_qhi);
    cudaGetSymbolAddress((void**)&qlo, g_qlo);
    cudaGetSymbolAddress((void**)&khi, g_khi);
    cudaGetSymbolAddress((void**)&klo, g_klo);
    cudaGetSymbolAddress((void**)&vhi, g_vhi);
    cudaGetSymbolAddress((void**)&vlo, g_vlo);

    cudaFuncSetAttribute(attn_mma_kernel,
                         cudaFuncAttributeMaxDynamicSharedMemorySize, SMEM_ATTN);

    const int NA4 = MROWS * DD / 4;   // 524288
    const int NW4 = DD * DD / 4;      // 65536
    const dim3 ggrid(DD / GN, MROWS / GM);   // (8, 32)

    // Q projection (epilogue emits bf16 hi/lo, pre-scaled by 1/sqrt(DK))
    split_bf16_kernel<<<NA4 / 256, 256>>>((const float4*)query, (uint2*)ahi, (uint2*)alo, NA4);
    split_bf16_kernel<<<NW4 / 256, 256>>>((const float4*)Wq, (uint2*)whi, (uint2*)wlo, NW4);
    mma_gemm_kernel<<<ggrid, 256, SMEM_GEMM>>>(ahi, alo, whi, wlo, bq,
                                               nullptr, qhi, qlo, 0.125f, MROWS, DD, DD);
    // K projection
    split_bf16_kernel<<<NA4 / 256, 256>>>((const float4*)key, (uint2*)ahi, (uint2*)alo, NA4);
    split_bf16_kernel<<<NW4 / 256, 256>>>((const float4*)Wk, (uint2*)whi, (uint2*)wlo, NW4);
    mma_gemm_kernel<<<ggrid, 256, SMEM_GEMM>>>(ahi, alo, whi, wlo, bk,
                                               nullptr, khi, klo, 1.0f, MROWS, DD, DD);
    // V projection
    split_bf16_kernel<<<NA4 / 256, 256>>>((const float4*)value, (uint2*)ahi, (uint2*)alo, NA4);
    split_bf16_kernel<<<NW4 / 256, 256>>>((const float4*)Wv, (uint2*)whi, (uint2*)wlo, NW4);
    mma_gemm_kernel<<<ggrid, 256, SMEM_GEMM>>>(ahi, alo, whi, wlo, bv,
                                               nullptr, vhi, vlo, 1.0f, MROWS, DD, DD);

    // attention (tensor cores)
    const dim3 agrid(SS / 64, BB * HH);   // (32, 16)
    attn_mma_kernel<<<agrid, 128, SMEM_ATTN>>>(qhi, qlo, khi, klo, vhi, vlo, gx);

    // output projection (fp32 epilogue)
    split_bf16_kernel<<<NA4 / 256, 256>>>((const float4*)gx, (uint2*)ahi, (uint2*)alo, NA4);
    split_bf16_kernel<<<NW4 / 256, 256>>>((const float4*)Wo, (uint2*)whi, (uint2*)wlo, NW4);
    mma_gemm_kernel<<<ggrid, 256, SMEM_GEMM>>>(ahi, alo, whi, wlo, bo,
                                               out, nullptr, nullptr, 1.0f, MROWS, DD, DD);
}